// round 8
// baseline (speedup 1.0000x reference)
#include <cuda_runtime.h>
#include <cuda_bf16.h>
#include <math.h>
#include <float.h>
#include <stdint.h>

#define N_ROWS 32768
#define M_COLS 2048
#define DIM    128
#define HEADS  8
#define NTILES 16          // M_COLS / 128
#define NSLOTS 16

// ---------------- scratch ----------------
__device__ float    g_W[DIM * DIM];
__device__ float    g_bsum[DIM];
__device__ float    g_G[M_COLS * DIM];
__device__ float    g_beta[M_COLS];
__device__ float    g_tmax[(size_t)N_ROWS * NTILES];
__device__ float    g_tsum[(size_t)N_ROWS * NTILES];
__device__ uint32_t g_cndcnt[(size_t)N_ROWS * NTILES];
__device__ uint4    g_cnd[(size_t)N_ROWS * NTILES * NSLOTS];   // {bits, j, logit, 0}, 128 MB
__device__ int      g_idx[N_ROWS];
__device__ float    g_acc[M_COLS * DIM];

// ---------------- K0a ----------------
__global__ void __launch_bounds__(128) prep_Wb_kernel(const float* __restrict__ Wq,
                                                      const float* __restrict__ bq) {
    int i = blockIdx.x, j = threadIdx.x;
    float s = 0.f;
#pragma unroll
    for (int h = 0; h < HEADS; h++) s += Wq[(h * DIM + i) * DIM + j];
    g_W[i * DIM + j] = s;
    if (i == 0) {
        float t = 0.f;
#pragma unroll
        for (int h = 0; h < HEADS; h++) t += bq[h * DIM + j];
        g_bsum[j] = 2.0f * t;
    }
}

// ---------------- K0b ----------------
__global__ void __launch_bounds__(128) prep_G_kernel(const float* __restrict__ c) {
    int m = blockIdx.x, kq = threadIdx.x;
    __shared__ float cs[DIM];
    __shared__ float red[DIM];
    cs[kq] = c[m * DIM + kq];
    __syncthreads();
    const float inv = 0.08838834764831845f;
    float s = 0.f;
#pragma unroll 8
    for (int j = 0; j < DIM; j++) s = fmaf(cs[j], g_W[j * DIM + kq], s);
    g_G[m * DIM + kq] = s * inv;
    red[kq] = cs[kq] * g_bsum[kq];
    __syncthreads();
    for (int st = 64; st > 0; st >>= 1) {
        if (kq < st) red[kq] += red[kq + st];
        __syncthreads();
    }
    if (kq == 0) g_beta[m] = red[0] * inv;
}

// ================= warp-MMA helpers =================
__device__ __forceinline__ uint32_t smem_u32(const void* p) {
    uint32_t a;
    asm("{ .reg .u64 t; cvta.to.shared.u64 t, %1; cvt.u32.u64 %0, t; }" : "=r"(a) : "l"(p));
    return a;
}
__device__ __forceinline__ void ldsm_x4(uint32_t* r, uint32_t addr) {
    asm volatile("ldmatrix.sync.aligned.m8n8.x4.shared.b16 {%0,%1,%2,%3}, [%4];"
                 : "=r"(r[0]), "=r"(r[1]), "=r"(r[2]), "=r"(r[3]) : "r"(addr));
}
__device__ __forceinline__ void mma16816(float* c, const uint32_t* a, const uint32_t* b) {
    asm volatile(
        "mma.sync.aligned.m16n8k16.row.col.f32.bf16.bf16.f32 "
        "{%0,%1,%2,%3}, {%4,%5,%6,%7}, {%8,%9}, {%0,%1,%2,%3};"
        : "+f"(c[0]), "+f"(c[1]), "+f"(c[2]), "+f"(c[3])
        : "r"(a[0]), "r"(a[1]), "r"(a[2]), "r"(a[3]), "r"(b[0]), "r"(b[1]));
}
__device__ __forceinline__ void split_pack(const float* v, uint32_t* hp, uint32_t* lp) {
#pragma unroll
    for (int q = 0; q < 2; q++) {
        __nv_bfloat16 h0 = __float2bfloat16_rn(v[2 * q]);
        __nv_bfloat16 h1 = __float2bfloat16_rn(v[2 * q + 1]);
        __nv_bfloat16 l0 = __float2bfloat16_rn(v[2 * q] - __bfloat162float(h0));
        __nv_bfloat16 l1 = __float2bfloat16_rn(v[2 * q + 1] - __bfloat162float(h1));
        hp[q] = ((uint32_t)__bfloat16_as_ushort(h1) << 16) | __bfloat16_as_ushort(h0);
        lp[q] = ((uint32_t)__bfloat16_as_ushort(l1) << 16) | __bfloat16_as_ushort(l0);
    }
}

// ---------------- threefry2x32 (JAX, key=(0,42)) ----------------
__device__ __forceinline__ void threefry2x32_042(uint32_t x0, uint32_t x1,
                                                 uint32_t& o0, uint32_t& o1) {
    const uint32_t KS0 = 0u, KS1 = 42u, KS2 = 0x1BD11BDAu ^ 42u;
    x0 += KS0; x1 += KS1;
#define TF_R(r) { x0 += x1; x1 = __funnelshift_l(x1, x1, r); x1 ^= x0; }
    TF_R(13) TF_R(15) TF_R(26) TF_R(6)   x0 += KS1; x1 += KS2 + 1u;
    TF_R(17) TF_R(29) TF_R(16) TF_R(24)  x0 += KS2; x1 += KS0 + 2u;
    TF_R(13) TF_R(15) TF_R(26) TF_R(6)   x0 += KS0; x1 += KS1 + 3u;
    TF_R(17) TF_R(29) TF_R(16) TF_R(24)  x0 += KS1; x1 += KS2 + 4u;
    TF_R(13) TF_R(15) TF_R(26) TF_R(6)   x0 += KS2; x1 += KS0 + 5u;
#undef TF_R
    o0 = x0; o1 = x1;
}
__device__ __forceinline__ uint32_t tf_bits(uint32_t f) {
    uint32_t o0, o1;
    threefry2x32_042(0u, f, o0, o1);
    return o0 ^ o1;
}
__device__ __forceinline__ float gumbel_from_bits(uint32_t bits) {
    float u = __uint_as_float((bits >> 9) | 0x3f800000u) - 1.0f;
    u = fmaxf(u, 1.17549435e-38f);
    return -logf(-logf(u));
}

// ---------------- K2: fused GEMM + per-tile softmax stats + gumbel candidates ------
// CTA tile 128x128, K=128 resident. smem: A_hi|A_lo|B_hi|B_lo, [128][136] bf16.
#define LDPAD 136
#define TILE_ELEMS (128 * LDPAD)
#define TILE_BYTES (TILE_ELEMS * 2)
#define GEMM_SMEM_BYTES (4 * TILE_BYTES)
#define BPAD 130   // sBits row stride (u32)

__global__ void __launch_bounds__(256) logits_mma_kernel(const float* __restrict__ x1,
                                                         const float* __restrict__ kk) {
    extern __shared__ __nv_bfloat16 sm_[];
    __nv_bfloat16* sAh = sm_;
    __nv_bfloat16* sAl = sm_ + TILE_ELEMS;
    __nv_bfloat16* sBh = sm_ + 2 * TILE_ELEMS;
    __nv_bfloat16* sBl = sm_ + 3 * TILE_ELEMS;
    __shared__ float sBeta[128];
    __shared__ float sMax[4][128];
    __shared__ float sSum[4][128];
    __shared__ uint32_t sBmaxS[4][128];
    __shared__ float sRowMax[128];
    __shared__ uint32_t sThr[128];
    __shared__ int sCnt[128];

    const int tid = threadIdx.x;
    const int row0 = blockIdx.y * 128;
    const int col0 = blockIdx.x * 128;
    const int bx = blockIdx.x;

    if (tid < 128) sBeta[tid] = g_beta[col0 + tid];

    // ---- load + split A = x1+k ----
#pragma unroll
    for (int i = 0; i < 16; i++) {
        int idx = i * 256 + tid;
        int r = idx >> 5;
        int c4 = (idx & 31) * 4;
        float4 a4 = *(const float4*)(x1 + (size_t)(row0 + r) * DIM + c4);
        float4 b4 = *(const float4*)(kk + (size_t)(row0 + r) * DIM + c4);
        float v[4] = {a4.x + b4.x, a4.y + b4.y, a4.z + b4.z, a4.w + b4.w};
        uint32_t hp[2], lp[2];
        split_pack(v, hp, lp);
        *(uint2*)(sAh + r * LDPAD + c4) = make_uint2(hp[0], hp[1]);
        *(uint2*)(sAl + r * LDPAD + c4) = make_uint2(lp[0], lp[1]);
    }
    // ---- load + split B = G rows ----
#pragma unroll
    for (int i = 0; i < 16; i++) {
        int idx = i * 256 + tid;
        int r = idx >> 5;
        int c4 = (idx & 31) * 4;
        float4 g4 = *(const float4*)(g_G + (size_t)(col0 + r) * DIM + c4);
        float v[4] = {g4.x, g4.y, g4.z, g4.w};
        uint32_t hp[2], lp[2];
        split_pack(v, hp, lp);
        *(uint2*)(sBh + r * LDPAD + c4) = make_uint2(hp[0], hp[1]);
        *(uint2*)(sBl + r * LDPAD + c4) = make_uint2(lp[0], lp[1]);
    }
    __syncthreads();

    // ---- warp tiling: 8 warps = 2 (m) x 4 (n); warp tile 64x32 ----
    const int wid = tid >> 5;
    const int lane = tid & 31;
    const int wm = wid & 1;
    const int wn = wid >> 1;
    const int mW = wm * 64;
    const int nW = wn * 32;

    const int g = lane >> 3, li = lane & 7;
    const int aRow = ((g & 1) << 3) + li, aCol = (g & 2) << 2;
    const int bRow = ((g >> 1) << 3) + li, bCol = (g & 1) << 3;

    const uint32_t aBaseH = smem_u32(sAh) + (uint32_t)(((mW + aRow) * LDPAD + aCol) * 2);
    const uint32_t bBaseH = smem_u32(sBh) + (uint32_t)(((nW + bRow) * LDPAD + bCol) * 2);
    const uint32_t LO_OFF = (uint32_t)TILE_BYTES;

    float acc[4][4][4];
#pragma unroll
    for (int mt = 0; mt < 4; mt++)
#pragma unroll
        for (int nt = 0; nt < 4; nt++)
#pragma unroll
            for (int q = 0; q < 4; q++) acc[mt][nt][q] = 0.f;

#pragma unroll
    for (int ks = 0; ks < 8; ks++) {
        uint32_t ah[16], bh[8], bl[8];
        const uint32_t kOff = (uint32_t)(ks * 32);
#pragma unroll
        for (int mt = 0; mt < 4; mt++) ldsm_x4(&ah[4 * mt], aBaseH + mt * (16 * LDPAD * 2) + kOff);
#pragma unroll
        for (int np = 0; np < 2; np++) ldsm_x4(&bh[4 * np], bBaseH + np * (16 * LDPAD * 2) + kOff);
#pragma unroll
        for (int mt = 0; mt < 4; mt++)
#pragma unroll
            for (int nt = 0; nt < 4; nt++) mma16816(acc[mt][nt], &ah[4 * mt], &bh[2 * nt]);
#pragma unroll
        for (int np = 0; np < 2; np++) ldsm_x4(&bl[4 * np], bBaseH + LO_OFF + np * (16 * LDPAD * 2) + kOff);
#pragma unroll
        for (int mt = 0; mt < 4; mt++)
#pragma unroll
            for (int nt = 0; nt < 4; nt++) mma16816(acc[mt][nt], &ah[4 * mt], &bl[2 * nt]);
#pragma unroll
        for (int mt = 0; mt < 4; mt++) ldsm_x4(&ah[4 * mt], aBaseH + LO_OFF + mt * (16 * LDPAD * 2) + kOff);
#pragma unroll
        for (int mt = 0; mt < 4; mt++)
#pragma unroll
            for (int nt = 0; nt < 4; nt++) mma16816(acc[mt][nt], &ah[4 * mt], &bh[2 * nt]);
    }

    // ================= fused epilogue =================
    const int rl = lane >> 2;          // row within 8
    const int cl = (lane & 3) * 2;     // col pair within 8
    __syncthreads();                   // mainloop tiles dead; smem reusable

    // ---- add beta: logits = acc + beta[n] ----
#pragma unroll
    for (int nt = 0; nt < 4; nt++) {
        int nl = nW + nt * 8 + cl;
        float b0 = sBeta[nl], b1 = sBeta[nl + 1];
#pragma unroll
        for (int mt = 0; mt < 4; mt++) {
            acc[mt][nt][0] += b0; acc[mt][nt][1] += b1;
            acc[mt][nt][2] += b0; acc[mt][nt][3] += b1;
        }
    }

    // ---- (1) per-row tile max ----
#pragma unroll
    for (int mt = 0; mt < 4; mt++)
#pragma unroll
        for (int qh = 0; qh < 2; qh++) {
            int rloc = mW + mt * 16 + rl + 8 * qh;
            float mx = -FLT_MAX;
#pragma unroll
            for (int nt = 0; nt < 4; nt++)
                mx = fmaxf(mx, fmaxf(acc[mt][nt][2 * qh], acc[mt][nt][2 * qh + 1]));
            mx = fmaxf(mx, __shfl_xor_sync(0xffffffffu, mx, 1));
            mx = fmaxf(mx, __shfl_xor_sync(0xffffffffu, mx, 2));
            if ((lane & 3) == 0) sMax[wn][rloc] = mx;
        }
    __syncthreads();
    if (tid < 128)
        sRowMax[tid] = fmaxf(fmaxf(sMax[0][tid], sMax[1][tid]),
                             fmaxf(sMax[2][tid], sMax[3][tid]));
    __syncthreads();

    // ---- (2) per-row tile expsum ----
#pragma unroll
    for (int mt = 0; mt < 4; mt++)
#pragma unroll
        for (int qh = 0; qh < 2; qh++) {
            int rloc = mW + mt * 16 + rl + 8 * qh;
            float rm = sRowMax[rloc];
            float s = 0.f;
#pragma unroll
            for (int nt = 0; nt < 4; nt++)
                s += expf(acc[mt][nt][2 * qh] - rm) + expf(acc[mt][nt][2 * qh + 1] - rm);
            s += __shfl_xor_sync(0xffffffffu, s, 1);
            s += __shfl_xor_sync(0xffffffffu, s, 2);
            if ((lane & 3) == 0) sSum[wn][rloc] = s;
        }
    __syncthreads();
    if (tid < 128) {
        size_t o = (size_t)(row0 + tid) * NTILES + bx;
        g_tmax[o] = sRowMax[tid];
        g_tsum[o] = sSum[0][tid] + sSum[1][tid] + sSum[2][tid] + sSum[3][tid];
    }

    // ---- (3) threefry bits: store to smem (reuse tile region), per-row bits max ----
    uint32_t* sBits = (uint32_t*)sm_;
#pragma unroll
    for (int mt = 0; mt < 4; mt++)
#pragma unroll
        for (int qh = 0; qh < 2; qh++) {
            int rloc = mW + mt * 16 + rl + 8 * qh;
            uint32_t fb = (uint32_t)(row0 + rloc) * (uint32_t)M_COLS + (uint32_t)col0;
            uint32_t bm = 0u;
#pragma unroll
            for (int nt = 0; nt < 4; nt++) {
                int nl = nW + nt * 8 + cl;
                uint32_t b0 = tf_bits(fb + (uint32_t)nl);
                uint32_t b1 = tf_bits(fb + (uint32_t)nl + 1u);
                *(uint2*)&sBits[rloc * BPAD + nl] = make_uint2(b0, b1);
                bm = max(bm, max(b0, b1));
            }
            bm = max(bm, __shfl_xor_sync(0xffffffffu, bm, 1));
            bm = max(bm, __shfl_xor_sync(0xffffffffu, bm, 2));
            if ((lane & 3) == 0) sBmaxS[wn][rloc] = bm;
        }
    __syncthreads();
    if (tid < 128) {
        uint32_t bm = max(max(sBmaxS[0][tid], sBmaxS[1][tid]),
                          max(sBmaxS[2][tid], sBmaxS[3][tid]));
        // tile candidate threshold: winner needs g >= g_tilemax - 1; relax 8 mantissa ulp
        float gmaxv = gumbel_from_bits(bm);
        float t = gmaxv - 1.0f;
        float u_t = expf(-expf(-t));
        float mtf = floorf(u_t * 8388608.0f) - 8.0f;
        sThr[tid] = (mtf <= 0.f) ? 0u : (uint32_t)mtf;
        sCnt[tid] = 0;
    }
    __syncthreads();

    // ---- (4) candidate harvest ----
#pragma unroll
    for (int mt = 0; mt < 4; mt++)
#pragma unroll
        for (int qh = 0; qh < 2; qh++) {
            int rloc = mW + mt * 16 + rl + 8 * qh;
            uint32_t thr = sThr[rloc];
#pragma unroll
            for (int nt = 0; nt < 4; nt++) {
                int nl = nW + nt * 8 + cl;
#pragma unroll
                for (int e = 0; e < 2; e++) {
                    uint32_t b = sBits[rloc * BPAD + nl + e];
                    if ((b >> 9) >= thr) {
                        float lg = acc[mt][nt][2 * qh + e];
                        int slot = atomicAdd(&sCnt[rloc], 1);
                        if (slot < NSLOTS) {
                            size_t o = ((size_t)(row0 + rloc) * NTILES + bx) * NSLOTS + slot;
                            g_cnd[o] = make_uint4(b, (uint32_t)(col0 + nl + e),
                                                  __float_as_uint(lg), 0u);
                        }
                    }
                }
            }
        }
    __syncthreads();
    if (tid < 128)
        g_cndcnt[(size_t)(row0 + tid) * NTILES + bx] = (uint32_t)min(sCnt[tid], NSLOTS);
}

// ---------------- K3: finalize — combine tiles, score candidates, argmax ----------------
__global__ void __launch_bounds__(256) finalize_kernel() {
    const int warp = threadIdx.x >> 5;
    const int lane = threadIdx.x & 31;
    const int n = blockIdx.x * 8 + warp;

    float tmax = -FLT_MAX, tsum = 0.f;
    if (lane < NTILES) {
        size_t o = (size_t)n * NTILES + lane;
        tmax = g_tmax[o];
        tsum = g_tsum[o];
    }
    float rmax = tmax;
#pragma unroll
    for (int st = 16; st > 0; st >>= 1)
        rmax = fmaxf(rmax, __shfl_xor_sync(0xffffffffu, rmax, st));
    float z = (lane < NTILES) ? tsum * expf(tmax - rmax) : 0.f;
#pragma unroll
    for (int st = 16; st > 0; st >>= 1)
        z += __shfl_xor_sync(0xffffffffu, z, st);
    const float invZ = 1.0f / z;

    float best = -FLT_MAX;
    int bj = 0x7FFFFFFF;
    if (lane < NTILES) {
        size_t tb = (size_t)n * NTILES + lane;
        int cnt = (int)g_cndcnt[tb];
#pragma unroll 4
        for (int s = 0; s < cnt; s++) {
            uint4 cd = g_cnd[tb * NSLOTS + s];
            float p = expf(__uint_as_float(cd.z) - rmax) * invZ;
            float sc = p + gumbel_from_bits(cd.x);
            int j = (int)cd.y;
            if (sc > best || (sc == best && j < bj)) { best = sc; bj = j; }
        }
    }
#pragma unroll
    for (int st = 16; st > 0; st >>= 1) {
        float ob = __shfl_xor_sync(0xffffffffu, best, st);
        int oj = __shfl_xor_sync(0xffffffffu, bj, st);
        if (ob > best || (ob == best && oj < bj)) { best = ob; bj = oj; }
    }
    if (lane == 0) g_idx[n] = bj;
}

// ---------------- K5/K6 ----------------
__global__ void __launch_bounds__(256) zero_acc_kernel() {
    g_acc[blockIdx.x * 256 + threadIdx.x] = 0.f;
}
__global__ void __launch_bounds__(256) scatter_kernel(const float* __restrict__ x1) {
    const int w = threadIdx.x >> 5;
    const int lane = threadIdx.x & 31;
    const int n = blockIdx.x * 8 + w;
    const int m = g_idx[n];
#pragma unroll
    for (int i = 0; i < 4; i++) {
        int d = lane + i * 32;
        atomicAdd(&g_acc[m * DIM + d], x1[(size_t)n * DIM + d]);
    }
}
__global__ void __launch_bounds__(128) final_kernel(const float* __restrict__ Wd,
                                                    const float* __restrict__ bd,
                                                    float* __restrict__ out) {
    const int m = blockIdx.x;
    const int j = threadIdx.x;
    __shared__ float a[DIM];
    a[j] = g_acc[m * DIM + j];
    __syncthreads();
    float s = bd[j];
#pragma unroll 8
    for (int kq = 0; kq < DIM; kq++) s = fmaf(a[kq], Wd[j * DIM + kq], s);
    out[m * DIM + j] = s;
}

// ---------------- launch ----------------
extern "C" void kernel_launch(void* const* d_in, const int* in_sizes, int n_in,
                              void* d_out, int out_size) {
    const float* x1 = (const float*)d_in[0];
    const float* k  = (const float*)d_in[1];
    const float* c  = (const float*)d_in[2];
    const float* Wq = (const float*)d_in[3];
    const float* bq = (const float*)d_in[4];
    const float* Wd = (const float*)d_in[5];
    const float* bd = (const float*)d_in[6];
    float* out = (float*)d_out;

    cudaFuncSetAttribute(logits_mma_kernel,
                         cudaFuncAttributeMaxDynamicSharedMemorySize, GEMM_SMEM_BYTES);

    prep_Wb_kernel<<<128, 128>>>(Wq, bq);
    prep_G_kernel<<<M_COLS, 128>>>(c);
    dim3 gl(M_COLS / 128, N_ROWS / 128);
    logits_mma_kernel<<<gl, 256, GEMM_SMEM_BYTES>>>(x1, k);
    finalize_kernel<<<N_ROWS / 8, 256>>>();
    zero_acc_kernel<<<M_COLS * DIM / 256, 256>>>();
    scatter_kernel<<<N_ROWS / 8, 256>>>(x1);
    final_kernel<<<M_COLS, 128>>>(Wd, bd, out);
}

// round 9
// speedup vs baseline: 1.1757x; 1.1757x over previous
#include <cuda_runtime.h>
#include <cuda_bf16.h>
#include <math.h>
#include <float.h>
#include <stdint.h>

#define N_ROWS 32768
#define M_COLS 2048
#define DIM    128
#define HEADS  8

// ---------------- scratch ----------------
__device__ float    g_W[DIM * DIM];
__device__ float    g_bsum[DIM];
__device__ float    g_G[M_COLS * DIM];
__device__ float    g_beta[M_COLS];
__device__ float    g_L[(size_t)N_ROWS * M_COLS];   // logits, 256 MB
__device__ int      g_idx[N_ROWS];
__device__ float    g_acc[M_COLS * DIM];

// ---------------- K0a ----------------
__global__ void __launch_bounds__(128) prep_Wb_kernel(const float* __restrict__ Wq,
                                                      const float* __restrict__ bq) {
    int i = blockIdx.x, j = threadIdx.x;
    float s = 0.f;
#pragma unroll
    for (int h = 0; h < HEADS; h++) s += Wq[(h * DIM + i) * DIM + j];
    g_W[i * DIM + j] = s;
    if (i == 0) {
        float t = 0.f;
#pragma unroll
        for (int h = 0; h < HEADS; h++) t += bq[h * DIM + j];
        g_bsum[j] = 2.0f * t;
    }
}

// ---------------- K0b ----------------
__global__ void __launch_bounds__(128) prep_G_kernel(const float* __restrict__ c) {
    int m = blockIdx.x, kq = threadIdx.x;
    __shared__ float cs[DIM];
    __shared__ float red[DIM];
    cs[kq] = c[m * DIM + kq];
    __syncthreads();
    const float inv = 0.08838834764831845f;
    float s = 0.f;
#pragma unroll 8
    for (int j = 0; j < DIM; j++) s = fmaf(cs[j], g_W[j * DIM + kq], s);
    g_G[m * DIM + kq] = s * inv;
    red[kq] = cs[kq] * g_bsum[kq];
    __syncthreads();
    for (int st = 64; st > 0; st >>= 1) {
        if (kq < st) red[kq] += red[kq + st];
        __syncthreads();
    }
    if (kq == 0) g_beta[m] = red[0] * inv;
}

// ================= warp-MMA helpers =================
__device__ __forceinline__ uint32_t smem_u32(const void* p) {
    uint32_t a;
    asm("{ .reg .u64 t; cvta.to.shared.u64 t, %1; cvt.u32.u64 %0, t; }" : "=r"(a) : "l"(p));
    return a;
}
__device__ __forceinline__ void ldsm_x4(uint32_t* r, uint32_t addr) {
    asm volatile("ldmatrix.sync.aligned.m8n8.x4.shared.b16 {%0,%1,%2,%3}, [%4];"
                 : "=r"(r[0]), "=r"(r[1]), "=r"(r[2]), "=r"(r[3]) : "r"(addr));
}
__device__ __forceinline__ void mma16816(float* c, const uint32_t* a, const uint32_t* b) {
    asm volatile(
        "mma.sync.aligned.m16n8k16.row.col.f32.bf16.bf16.f32 "
        "{%0,%1,%2,%3}, {%4,%5,%6,%7}, {%8,%9}, {%0,%1,%2,%3};"
        : "+f"(c[0]), "+f"(c[1]), "+f"(c[2]), "+f"(c[3])
        : "r"(a[0]), "r"(a[1]), "r"(a[2]), "r"(a[3]), "r"(b[0]), "r"(b[1]));
}
__device__ __forceinline__ void split_pack(const float* v, uint32_t* hp, uint32_t* lp) {
#pragma unroll
    for (int q = 0; q < 2; q++) {
        __nv_bfloat16 h0 = __float2bfloat16_rn(v[2 * q]);
        __nv_bfloat16 h1 = __float2bfloat16_rn(v[2 * q + 1]);
        __nv_bfloat16 l0 = __float2bfloat16_rn(v[2 * q] - __bfloat162float(h0));
        __nv_bfloat16 l1 = __float2bfloat16_rn(v[2 * q + 1] - __bfloat162float(h1));
        hp[q] = ((uint32_t)__bfloat16_as_ushort(h1) << 16) | __bfloat16_as_ushort(h0);
        lp[q] = ((uint32_t)__bfloat16_as_ushort(l1) << 16) | __bfloat16_as_ushort(l0);
    }
}

// ---------------- K2: logits = (x1+k) @ G^T + beta, bf16-split 3-pass mma.sync ------
// CTA tile 128x128, K=128 resident; 512 threads = 16 warps (4m x 4n), warp tile 32x32.
#define LDPAD 136
#define TILE_ELEMS (128 * LDPAD)
#define TILE_BYTES (TILE_ELEMS * 2)
#define GEMM_SMEM_BYTES (4 * TILE_BYTES)

__global__ void __launch_bounds__(512) logits_mma_kernel(const float* __restrict__ x1,
                                                         const float* __restrict__ kk) {
    extern __shared__ __nv_bfloat16 sm_[];
    __nv_bfloat16* sAh = sm_;
    __nv_bfloat16* sAl = sm_ + TILE_ELEMS;
    __nv_bfloat16* sBh = sm_ + 2 * TILE_ELEMS;
    __nv_bfloat16* sBl = sm_ + 3 * TILE_ELEMS;
    __shared__ float sBeta[128];

    const int tid = threadIdx.x;
    const int row0 = blockIdx.y * 128;
    const int col0 = blockIdx.x * 128;

    if (tid < 128) sBeta[tid] = g_beta[col0 + tid];

    // ---- load + split A = x1+k (4096 float4 slots, 8 per thread) ----
#pragma unroll
    for (int i = 0; i < 8; i++) {
        int idx = i * 512 + tid;
        int r = idx >> 5;
        int c4 = (idx & 31) * 4;
        float4 a4 = *(const float4*)(x1 + (size_t)(row0 + r) * DIM + c4);
        float4 b4 = *(const float4*)(kk + (size_t)(row0 + r) * DIM + c4);
        float v[4] = {a4.x + b4.x, a4.y + b4.y, a4.z + b4.z, a4.w + b4.w};
        uint32_t hp[2], lp[2];
        split_pack(v, hp, lp);
        *(uint2*)(sAh + r * LDPAD + c4) = make_uint2(hp[0], hp[1]);
        *(uint2*)(sAl + r * LDPAD + c4) = make_uint2(lp[0], lp[1]);
    }
    // ---- load + split B = G rows ----
#pragma unroll
    for (int i = 0; i < 8; i++) {
        int idx = i * 512 + tid;
        int r = idx >> 5;
        int c4 = (idx & 31) * 4;
        float4 g4 = *(const float4*)(g_G + (size_t)(col0 + r) * DIM + c4);
        float v[4] = {g4.x, g4.y, g4.z, g4.w};
        uint32_t hp[2], lp[2];
        split_pack(v, hp, lp);
        *(uint2*)(sBh + r * LDPAD + c4) = make_uint2(hp[0], hp[1]);
        *(uint2*)(sBl + r * LDPAD + c4) = make_uint2(lp[0], lp[1]);
    }
    __syncthreads();

    // ---- warp tiling: 16 warps = 4 (m) x 4 (n); warp tile 32x32 ----
    const int wid = tid >> 5;
    const int lane = tid & 31;
    const int wm = wid & 3;
    const int wn = wid >> 2;
    const int mW = wm * 32;
    const int nW = wn * 32;

    const int g = lane >> 3, li = lane & 7;
    const int aRow = ((g & 1) << 3) + li, aCol = (g & 2) << 2;
    const int bRow = ((g >> 1) << 3) + li, bCol = (g & 1) << 3;

    const uint32_t aBaseH = smem_u32(sAh) + (uint32_t)(((mW + aRow) * LDPAD + aCol) * 2);
    const uint32_t bBaseH = smem_u32(sBh) + (uint32_t)(((nW + bRow) * LDPAD + bCol) * 2);
    const uint32_t LO_OFF = (uint32_t)TILE_BYTES;

    float acc[2][4][4];
#pragma unroll
    for (int mt = 0; mt < 2; mt++)
#pragma unroll
        for (int nt = 0; nt < 4; nt++)
#pragma unroll
            for (int q = 0; q < 4; q++) acc[mt][nt][q] = 0.f;

#pragma unroll
    for (int ks = 0; ks < 8; ks++) {
        uint32_t ah[8], bh[8], bl[8];
        const uint32_t kOff = (uint32_t)(ks * 32);
#pragma unroll
        for (int mt = 0; mt < 2; mt++) ldsm_x4(&ah[4 * mt], aBaseH + mt * (16 * LDPAD * 2) + kOff);
#pragma unroll
        for (int np = 0; np < 2; np++) ldsm_x4(&bh[4 * np], bBaseH + np * (16 * LDPAD * 2) + kOff);
        // pass 0: Ahi * Bhi
#pragma unroll
        for (int mt = 0; mt < 2; mt++)
#pragma unroll
            for (int nt = 0; nt < 4; nt++) mma16816(acc[mt][nt], &ah[4 * mt], &bh[2 * nt]);
        // pass 1: Ahi * Blo
#pragma unroll
        for (int np = 0; np < 2; np++) ldsm_x4(&bl[4 * np], bBaseH + LO_OFF + np * (16 * LDPAD * 2) + kOff);
#pragma unroll
        for (int mt = 0; mt < 2; mt++)
#pragma unroll
            for (int nt = 0; nt < 4; nt++) mma16816(acc[mt][nt], &ah[4 * mt], &bl[2 * nt]);
        // pass 2: Alo * Bhi (reuse ah regs)
#pragma unroll
        for (int mt = 0; mt < 2; mt++) ldsm_x4(&ah[4 * mt], aBaseH + LO_OFF + mt * (16 * LDPAD * 2) + kOff);
#pragma unroll
        for (int mt = 0; mt < 2; mt++)
#pragma unroll
            for (int nt = 0; nt < 4; nt++) mma16816(acc[mt][nt], &ah[4 * mt], &bh[2 * nt]);
    }

    // ---- epilogue ----
    const int rl = lane >> 2;
    const int cl = (lane & 3) * 2;
#pragma unroll
    for (int mt = 0; mt < 2; mt++) {
#pragma unroll
        for (int nt = 0; nt < 4; nt++) {
            int m = row0 + mW + mt * 16 + rl;
            int nn = nW + nt * 8 + cl;
            float b0 = sBeta[nn], b1 = sBeta[nn + 1];
            float* p0 = g_L + (size_t)m * M_COLS + col0 + nn;
            float* p1 = g_L + (size_t)(m + 8) * M_COLS + col0 + nn;
            *(float2*)p0 = make_float2(acc[mt][nt][0] + b0, acc[mt][nt][1] + b1);
            *(float2*)p1 = make_float2(acc[mt][nt][2] + b0, acc[mt][nt][3] + b1);
        }
    }
}

// ---------------- threefry2x32 (JAX, key=(0,42)) ----------------
__device__ __forceinline__ void threefry2x32_042(uint32_t x0, uint32_t x1,
                                                 uint32_t& o0, uint32_t& o1) {
    const uint32_t KS0 = 0u, KS1 = 42u, KS2 = 0x1BD11BDAu ^ 42u;
    x0 += KS0; x1 += KS1;
#define TF_R(r) { x0 += x1; x1 = __funnelshift_l(x1, x1, r); x1 ^= x0; }
    TF_R(13) TF_R(15) TF_R(26) TF_R(6)   x0 += KS1; x1 += KS2 + 1u;
    TF_R(17) TF_R(29) TF_R(16) TF_R(24)  x0 += KS2; x1 += KS0 + 2u;
    TF_R(13) TF_R(15) TF_R(26) TF_R(6)   x0 += KS0; x1 += KS1 + 3u;
    TF_R(17) TF_R(29) TF_R(16) TF_R(24)  x0 += KS1; x1 += KS2 + 4u;
    TF_R(13) TF_R(15) TF_R(26) TF_R(6)   x0 += KS2; x1 += KS0 + 5u;
#undef TF_R
    o0 = x0; o1 = x1;
}
__device__ __forceinline__ uint32_t tf_bits(uint32_t f) {
    uint32_t o0, o1;
    threefry2x32_042(0u, f, o0, o1);
    return o0 ^ o1;
}
__device__ __forceinline__ float gumbel_from_bits(uint32_t bits) {
    float u = __uint_as_float((bits >> 9) | 0x3f800000u) - 1.0f;
    u = fmaxf(u, 1.17549435e-38f);
    return -logf(-logf(u));
}

// ---------------- K3: inline threefry + softmax + candidate argmax (shfl reductions) ---
__global__ void __launch_bounds__(256) softmax_argmax_kernel() {
    const int n = blockIdx.x;
    const int tid = threadIdx.x;
    const int wid = tid >> 5;
    const int lane = tid & 31;
    const float* row = g_L + (size_t)n * M_COLS;

    float4 v0 = *(const float4*)(row + tid * 8);
    float4 v1 = *(const float4*)(row + tid * 8 + 4);
    float ev[8] = {v0.x, v0.y, v0.z, v0.w, v1.x, v1.y, v1.z, v1.w};

    uint32_t bits[8];
    const uint32_t fbase = (uint32_t)(n * M_COLS) + (uint32_t)(tid * 8);
#pragma unroll
    for (int i = 0; i < 8; i++) bits[i] = tf_bits(fbase + (uint32_t)i);

    __shared__ float sMaxW[8], sSumW[8], sBestW[8];
    __shared__ uint32_t sBmaxW[8];
    __shared__ int sIdxW[8];

    // --- fused (logit max, bits max): warp shfl ladder + 8-slot combine ---
    float lmax = ev[0];
    uint32_t bmax = bits[0];
#pragma unroll
    for (int i = 1; i < 8; i++) { lmax = fmaxf(lmax, ev[i]); bmax = max(bmax, bits[i]); }
#pragma unroll
    for (int st = 16; st > 0; st >>= 1) {
        lmax = fmaxf(lmax, __shfl_xor_sync(0xffffffffu, lmax, st));
        bmax = max(bmax, __shfl_xor_sync(0xffffffffu, bmax, st));
    }
    if (lane == 0) { sMaxW[wid] = lmax; sBmaxW[wid] = bmax; }
    __syncthreads();
    float rmax = sMaxW[0];
    uint32_t rbmax = sBmaxW[0];
#pragma unroll
    for (int w = 1; w < 8; w++) {
        rmax = fmaxf(rmax, sMaxW[w]);
        rbmax = max(rbmax, sBmaxW[w]);
    }

    // --- expsum: warp shfl + 8-slot combine ---
    float ls = 0.f;
#pragma unroll
    for (int i = 0; i < 8; i++) { ev[i] = expf(ev[i] - rmax); ls += ev[i]; }
#pragma unroll
    for (int st = 16; st > 0; st >>= 1) ls += __shfl_xor_sync(0xffffffffu, ls, st);
    if (lane == 0) sSumW[wid] = ls;
    __syncthreads();
    float z = sSumW[0];
#pragma unroll
    for (int w = 1; w < 8; w++) z += sSumW[w];
    const float rZ = 1.0f / z;

    // --- candidate threshold: winner needs g >= g_max - 1; relax 8 mantissa ulp ---
    float gmaxv = gumbel_from_bits(rbmax);
    float t = gmaxv - 1.0f;
    float u_t = expf(-expf(-t));
    float mtf = floorf(u_t * 8388608.0f) - 8.0f;
    uint32_t mant_t = (mtf <= 0.f) ? 0u : (uint32_t)mtf;

    // --- candidate-only scoring ---
    float best = -FLT_MAX;
    int bi = 0x7FFFFFFF;
#pragma unroll
    for (int i = 0; i < 8; i++) {
        if ((bits[i] >> 9) >= mant_t) {
            float s = ev[i] * rZ + gumbel_from_bits(bits[i]);
            if (s > best) { best = s; bi = tid * 8 + i; }  // ascending j keeps first index
        }
    }
#pragma unroll
    for (int st = 16; st > 0; st >>= 1) {
        float ob = __shfl_xor_sync(0xffffffffu, best, st);
        int oj = __shfl_xor_sync(0xffffffffu, bi, st);
        if (ob > best || (ob == best && oj < bi)) { best = ob; bi = oj; }
    }
    if (lane == 0) { sBestW[wid] = best; sIdxW[wid] = bi; }
    __syncthreads();
    if (tid == 0) {
        float b = sBestW[0];
        int j = sIdxW[0];
#pragma unroll
        for (int w = 1; w < 8; w++) {
            float ob = sBestW[w]; int oj = sIdxW[w];
            if (ob > b || (ob == b && oj < j)) { b = ob; j = oj; }
        }
        g_idx[n] = j;
    }
}

// ---------------- K5/K6 ----------------
__global__ void __launch_bounds__(256) zero_acc_kernel() {
    g_acc[blockIdx.x * 256 + threadIdx.x] = 0.f;
}
__global__ void __launch_bounds__(256) scatter_kernel(const float* __restrict__ x1) {
    const int w = threadIdx.x >> 5;
    const int lane = threadIdx.x & 31;
    const int n = blockIdx.x * 8 + w;
    const int m = g_idx[n];
#pragma unroll
    for (int i = 0; i < 4; i++) {
        int d = lane + i * 32;
        atomicAdd(&g_acc[m * DIM + d], x1[(size_t)n * DIM + d]);
    }
}
__global__ void __launch_bounds__(128) final_kernel(const float* __restrict__ Wd,
                                                    const float* __restrict__ bd,
                                                    float* __restrict__ out) {
    const int m = blockIdx.x;
    const int j = threadIdx.x;
    __shared__ float a[DIM];
    a[j] = g_acc[m * DIM + j];
    __syncthreads();
    float s = bd[j];
#pragma unroll 8
    for (int kq = 0; kq < DIM; kq++) s = fmaf(a[kq], Wd[j * DIM + kq], s);
    out[m * DIM + j] = s;
}

// ---------------- launch ----------------
extern "C" void kernel_launch(void* const* d_in, const int* in_sizes, int n_in,
                              void* d_out, int out_size) {
    const float* x1 = (const float*)d_in[0];
    const float* k  = (const float*)d_in[1];
    const float* c  = (const float*)d_in[2];
    const float* Wq = (const float*)d_in[3];
    const float* bq = (const float*)d_in[4];
    const float* Wd = (const float*)d_in[5];
    const float* bd = (const float*)d_in[6];
    float* out = (float*)d_out;

    cudaFuncSetAttribute(logits_mma_kernel,
                         cudaFuncAttributeMaxDynamicSharedMemorySize, GEMM_SMEM_BYTES);

    prep_Wb_kernel<<<128, 128>>>(Wq, bq);
    prep_G_kernel<<<M_COLS, 128>>>(c);
    dim3 gl(M_COLS / 128, N_ROWS / 128);
    logits_mma_kernel<<<gl, 512, GEMM_SMEM_BYTES>>>(x1, k);
    softmax_argmax_kernel<<<N_ROWS, 256>>>();
    zero_acc_kernel<<<M_COLS * DIM / 256, 256>>>();
    scatter_kernel<<<N_ROWS / 8, 256>>>(x1);
    final_kernel<<<M_COLS, 128>>>(Wd, bd, out);
}

// round 10
// speedup vs baseline: 1.2771x; 1.0862x over previous
#include <cuda_runtime.h>
#include <cuda_bf16.h>
#include <math.h>
#include <float.h>
#include <stdint.h>

#define N_ROWS 32768
#define M_COLS 2048
#define DIM    128
#define HEADS  8

// ---------------- scratch ----------------
__device__ float         g_W[DIM * DIM];
__device__ float         g_bsum[DIM];
__device__ float         g_G[M_COLS * DIM];
__device__ float         g_beta[M_COLS];
__device__ __nv_bfloat16 g_Ah[(size_t)N_ROWS * DIM];   // hi(x1+k), 8 MB
__device__ __nv_bfloat16 g_Al[(size_t)N_ROWS * DIM];   // lo(x1+k)
__device__ __nv_bfloat16 g_Gh[M_COLS * DIM];
__device__ __nv_bfloat16 g_Gl[M_COLS * DIM];
__device__ float         g_L[(size_t)N_ROWS * M_COLS]; // logits, 256 MB
__device__ int           g_idx[N_ROWS];
__device__ float         g_acc[M_COLS * DIM];

// ---------------- K0a ----------------
__global__ void __launch_bounds__(128) prep_Wb_kernel(const float* __restrict__ Wq,
                                                      const float* __restrict__ bq) {
    int i = blockIdx.x, j = threadIdx.x;
    float s = 0.f;
#pragma unroll
    for (int h = 0; h < HEADS; h++) s += Wq[(h * DIM + i) * DIM + j];
    g_W[i * DIM + j] = s;
    if (i == 0) {
        float t = 0.f;
#pragma unroll
        for (int h = 0; h < HEADS; h++) t += bq[h * DIM + j];
        g_bsum[j] = 2.0f * t;
    }
}

// ---------------- K0b ----------------
__global__ void __launch_bounds__(128) prep_G_kernel(const float* __restrict__ c) {
    int m = blockIdx.x, kq = threadIdx.x;
    __shared__ float cs[DIM];
    __shared__ float red[DIM];
    cs[kq] = c[m * DIM + kq];
    __syncthreads();
    const float inv = 0.08838834764831845f;
    float s = 0.f;
#pragma unroll 8
    for (int j = 0; j < DIM; j++) s = fmaf(cs[j], g_W[j * DIM + kq], s);
    g_G[m * DIM + kq] = s * inv;
    red[kq] = cs[kq] * g_bsum[kq];
    __syncthreads();
    for (int st = 64; st > 0; st >>= 1) {
        if (kq < st) red[kq] += red[kq + st];
        __syncthreads();
    }
    if (kq == 0) g_beta[m] = red[0] * inv;
}

// ---------------- bf16 split helpers ----------------
__device__ __forceinline__ void split4(const float* v, uint32_t* hp, uint32_t* lp) {
#pragma unroll
    for (int q = 0; q < 2; q++) {
        __nv_bfloat16 h0 = __float2bfloat16_rn(v[2 * q]);
        __nv_bfloat16 h1 = __float2bfloat16_rn(v[2 * q + 1]);
        __nv_bfloat16 l0 = __float2bfloat16_rn(v[2 * q] - __bfloat162float(h0));
        __nv_bfloat16 l1 = __float2bfloat16_rn(v[2 * q + 1] - __bfloat162float(h1));
        hp[q] = ((uint32_t)__bfloat16_as_ushort(h1) << 16) | __bfloat16_as_ushort(h0);
        lp[q] = ((uint32_t)__bfloat16_as_ushort(l1) << 16) | __bfloat16_as_ushort(l0);
    }
}

// ---------------- K1a: split x1+k -> g_Ah/g_Al (once) ----------------
__global__ void __launch_bounds__(256) prep_A_kernel(const float* __restrict__ x1,
                                                     const float* __restrict__ kk) {
    size_t idx = (size_t)blockIdx.x * 256 + threadIdx.x;   // float4 index
    float4 a4 = ((const float4*)x1)[idx];
    float4 b4 = ((const float4*)kk)[idx];
    float v[4] = {a4.x + b4.x, a4.y + b4.y, a4.z + b4.z, a4.w + b4.w};
    uint32_t hp[2], lp[2];
    split4(v, hp, lp);
    ((uint2*)g_Ah)[idx] = make_uint2(hp[0], hp[1]);
    ((uint2*)g_Al)[idx] = make_uint2(lp[0], lp[1]);
}

// ---------------- K1b: split G -> g_Gh/g_Gl ----------------
__global__ void __launch_bounds__(256) prep_GG_kernel() {
    size_t idx = (size_t)blockIdx.x * 256 + threadIdx.x;
    float4 g4 = ((const float4*)g_G)[idx];
    float v[4] = {g4.x, g4.y, g4.z, g4.w};
    uint32_t hp[2], lp[2];
    split4(v, hp, lp);
    ((uint2*)g_Gh)[idx] = make_uint2(hp[0], hp[1]);
    ((uint2*)g_Gl)[idx] = make_uint2(lp[0], lp[1]);
}

// ================= warp-MMA helpers =================
__device__ __forceinline__ uint32_t smem_u32(const void* p) {
    uint32_t a;
    asm("{ .reg .u64 t; cvta.to.shared.u64 t, %1; cvt.u32.u64 %0, t; }" : "=r"(a) : "l"(p));
    return a;
}
__device__ __forceinline__ void ldsm_x4(uint32_t* r, uint32_t addr) {
    asm volatile("ldmatrix.sync.aligned.m8n8.x4.shared.b16 {%0,%1,%2,%3}, [%4];"
                 : "=r"(r[0]), "=r"(r[1]), "=r"(r[2]), "=r"(r[3]) : "r"(addr));
}
__device__ __forceinline__ void mma16816(float* c, const uint32_t* a, const uint32_t* b) {
    asm volatile(
        "mma.sync.aligned.m16n8k16.row.col.f32.bf16.bf16.f32 "
        "{%0,%1,%2,%3}, {%4,%5,%6,%7}, {%8,%9}, {%0,%1,%2,%3};"
        : "+f"(c[0]), "+f"(c[1]), "+f"(c[2]), "+f"(c[3])
        : "r"(a[0]), "r"(a[1]), "r"(a[2]), "r"(a[3]), "r"(b[0]), "r"(b[1]));
}

// ---------------- K2: logits GEMM, tile 128x64, 2 CTAs/SM, preconverted bf16 --------
#define LDPAD 136
#define A_ELEMS (128 * LDPAD)     // 17408 bf16 -> 34816 B
#define B_ELEMS (64 * LDPAD)      //  8704 bf16 -> 17408 B
#define GEMM_SMEM_BYTES ((2 * A_ELEMS + 2 * B_ELEMS) * 2)   // 104448

__global__ void __launch_bounds__(256, 2) logits_mma_kernel() {
    extern __shared__ __nv_bfloat16 sm_[];
    __nv_bfloat16* sAh = sm_;
    __nv_bfloat16* sAl = sm_ + A_ELEMS;
    __nv_bfloat16* sBh = sm_ + 2 * A_ELEMS;
    __nv_bfloat16* sBl = sm_ + 2 * A_ELEMS + B_ELEMS;
    __shared__ float sBeta[64];

    const int tid = threadIdx.x;
    const int row0 = blockIdx.y * 128;
    const int col0 = blockIdx.x * 64;

    if (tid < 64) sBeta[tid] = g_beta[col0 + tid];

    // ---- load A hi/lo: 128x128 bf16 = 2048 uint4 per tile ----
#pragma unroll
    for (int i = 0; i < 8; i++) {
        int idx = i * 256 + tid;
        int r = idx >> 4;
        int c8 = (idx & 15) * 8;
        size_t go = (size_t)(row0 + r) * DIM + c8;
        *(uint4*)(sAh + r * LDPAD + c8) = *(const uint4*)(g_Ah + go);
        *(uint4*)(sAl + r * LDPAD + c8) = *(const uint4*)(g_Al + go);
    }
    // ---- load B hi/lo: 64x128 bf16 = 1024 uint4 per tile ----
#pragma unroll
    for (int i = 0; i < 4; i++) {
        int idx = i * 256 + tid;
        int r = idx >> 4;
        int c8 = (idx & 15) * 8;
        size_t go = (size_t)(col0 + r) * DIM + c8;
        *(uint4*)(sBh + r * LDPAD + c8) = *(const uint4*)(g_Gh + go);
        *(uint4*)(sBl + r * LDPAD + c8) = *(const uint4*)(g_Gl + go);
    }
    __syncthreads();

    // ---- warp tiling: 8 warps = 4 (m) x 2 (n); warp tile 32x32 ----
    const int wid = tid >> 5;
    const int lane = tid & 31;
    const int wm = wid & 3;
    const int wn = wid >> 2;
    const int mW = wm * 32;
    const int nW = wn * 32;

    const int g = lane >> 3, li = lane & 7;
    const int aRow = ((g & 1) << 3) + li, aCol = (g & 2) << 2;
    const int bRow = ((g >> 1) << 3) + li, bCol = (g & 1) << 3;

    const uint32_t aBaseH = smem_u32(sAh) + (uint32_t)(((mW + aRow) * LDPAD + aCol) * 2);
    const uint32_t bBaseH = smem_u32(sBh) + (uint32_t)(((nW + bRow) * LDPAD + bCol) * 2);
    const uint32_t A_LO = (uint32_t)(A_ELEMS * 2);
    const uint32_t B_LO = (uint32_t)(B_ELEMS * 2);

    float acc[2][4][4];
#pragma unroll
    for (int mt = 0; mt < 2; mt++)
#pragma unroll
        for (int nt = 0; nt < 4; nt++)
#pragma unroll
            for (int q = 0; q < 4; q++) acc[mt][nt][q] = 0.f;

#pragma unroll
    for (int ks = 0; ks < 8; ks++) {
        uint32_t ah[8], bh[8], bl[8];
        const uint32_t kOff = (uint32_t)(ks * 32);
#pragma unroll
        for (int mt = 0; mt < 2; mt++) ldsm_x4(&ah[4 * mt], aBaseH + mt * (16 * LDPAD * 2) + kOff);
#pragma unroll
        for (int np = 0; np < 2; np++) ldsm_x4(&bh[4 * np], bBaseH + np * (16 * LDPAD * 2) + kOff);
        // pass 0: Ahi * Bhi
#pragma unroll
        for (int mt = 0; mt < 2; mt++)
#pragma unroll
            for (int nt = 0; nt < 4; nt++) mma16816(acc[mt][nt], &ah[4 * mt], &bh[2 * nt]);
        // pass 1: Ahi * Blo
#pragma unroll
        for (int np = 0; np < 2; np++) ldsm_x4(&bl[4 * np], bBaseH + B_LO + np * (16 * LDPAD * 2) + kOff);
#pragma unroll
        for (int mt = 0; mt < 2; mt++)
#pragma unroll
            for (int nt = 0; nt < 4; nt++) mma16816(acc[mt][nt], &ah[4 * mt], &bl[2 * nt]);
        // pass 2: Alo * Bhi
#pragma unroll
        for (int mt = 0; mt < 2; mt++) ldsm_x4(&ah[4 * mt], aBaseH + A_LO + mt * (16 * LDPAD * 2) + kOff);
#pragma unroll
        for (int mt = 0; mt < 2; mt++)
#pragma unroll
            for (int nt = 0; nt < 4; nt++) mma16816(acc[mt][nt], &ah[4 * mt], &bh[2 * nt]);
    }

    // ---- epilogue ----
    const int rl = lane >> 2;
    const int cl = (lane & 3) * 2;
#pragma unroll
    for (int mt = 0; mt < 2; mt++) {
#pragma unroll
        for (int nt = 0; nt < 4; nt++) {
            int m = row0 + mW + mt * 16 + rl;
            int nn = nW + nt * 8 + cl;
            float b0 = sBeta[nn], b1 = sBeta[nn + 1];
            float* p0 = g_L + (size_t)m * M_COLS + col0 + nn;
            float* p1 = g_L + (size_t)(m + 8) * M_COLS + col0 + nn;
            *(float2*)p0 = make_float2(acc[mt][nt][0] + b0, acc[mt][nt][1] + b1);
            *(float2*)p1 = make_float2(acc[mt][nt][2] + b0, acc[mt][nt][3] + b1);
        }
    }
}

// ---------------- threefry2x32 (JAX, key=(0,42)) ----------------
__device__ __forceinline__ void threefry2x32_042(uint32_t x0, uint32_t x1,
                                                 uint32_t& o0, uint32_t& o1) {
    const uint32_t KS0 = 0u, KS1 = 42u, KS2 = 0x1BD11BDAu ^ 42u;
    x0 += KS0; x1 += KS1;
#define TF_R(r) { x0 += x1; x1 = __funnelshift_l(x1, x1, r); x1 ^= x0; }
    TF_R(13) TF_R(15) TF_R(26) TF_R(6)   x0 += KS1; x1 += KS2 + 1u;
    TF_R(17) TF_R(29) TF_R(16) TF_R(24)  x0 += KS2; x1 += KS0 + 2u;
    TF_R(13) TF_R(15) TF_R(26) TF_R(6)   x0 += KS0; x1 += KS1 + 3u;
    TF_R(17) TF_R(29) TF_R(16) TF_R(24)  x0 += KS1; x1 += KS2 + 4u;
    TF_R(13) TF_R(15) TF_R(26) TF_R(6)   x0 += KS2; x1 += KS0 + 5u;
#undef TF_R
    o0 = x0; o1 = x1;
}
__device__ __forceinline__ uint32_t tf_bits(uint32_t f) {
    uint32_t o0, o1;
    threefry2x32_042(0u, f, o0, o1);
    return o0 ^ o1;
}
__device__ __forceinline__ float gumbel_from_bits(uint32_t bits) {
    float u = __uint_as_float((bits >> 9) | 0x3f800000u) - 1.0f;
    u = fmaxf(u, 1.17549435e-38f);
    return -logf(-logf(u));
}

// ---------------- K3: inline threefry + softmax + candidate argmax ----------------
__global__ void __launch_bounds__(256) softmax_argmax_kernel() {
    const int n = blockIdx.x;
    const int tid = threadIdx.x;
    const int wid = tid >> 5;
    const int lane = tid & 31;
    const float* row = g_L + (size_t)n * M_COLS;

    float4 v0 = *(const float4*)(row + tid * 8);
    float4 v1 = *(const float4*)(row + tid * 8 + 4);
    float ev[8] = {v0.x, v0.y, v0.z, v0.w, v1.x, v1.y, v1.z, v1.w};

    uint32_t bits[8];
    const uint32_t fbase = (uint32_t)(n * M_COLS) + (uint32_t)(tid * 8);
#pragma unroll
    for (int i = 0; i < 8; i++) bits[i] = tf_bits(fbase + (uint32_t)i);

    __shared__ float sMaxW[8], sSumW[8], sBestW[8];
    __shared__ uint32_t sBmaxW[8];
    __shared__ int sIdxW[8];

    float lmax = ev[0];
    uint32_t bmax = bits[0];
#pragma unroll
    for (int i = 1; i < 8; i++) { lmax = fmaxf(lmax, ev[i]); bmax = max(bmax, bits[i]); }
#pragma unroll
    for (int st = 16; st > 0; st >>= 1) {
        lmax = fmaxf(lmax, __shfl_xor_sync(0xffffffffu, lmax, st));
        bmax = max(bmax, __shfl_xor_sync(0xffffffffu, bmax, st));
    }
    if (lane == 0) { sMaxW[wid] = lmax; sBmaxW[wid] = bmax; }
    __syncthreads();
    float rmax = sMaxW[0];
    uint32_t rbmax = sBmaxW[0];
#pragma unroll
    for (int w = 1; w < 8; w++) {
        rmax = fmaxf(rmax, sMaxW[w]);
        rbmax = max(rbmax, sBmaxW[w]);
    }

    float ls = 0.f;
#pragma unroll
    for (int i = 0; i < 8; i++) { ev[i] = expf(ev[i] - rmax); ls += ev[i]; }
#pragma unroll
    for (int st = 16; st > 0; st >>= 1) ls += __shfl_xor_sync(0xffffffffu, ls, st);
    if (lane == 0) sSumW[wid] = ls;
    __syncthreads();
    float z = sSumW[0];
#pragma unroll
    for (int w = 1; w < 8; w++) z += sSumW[w];
    const float rZ = 1.0f / z;

    float gmaxv = gumbel_from_bits(rbmax);
    float t = gmaxv - 1.0f;
    float u_t = expf(-expf(-t));
    float mtf = floorf(u_t * 8388608.0f) - 8.0f;
    uint32_t mant_t = (mtf <= 0.f) ? 0u : (uint32_t)mtf;

    float best = -FLT_MAX;
    int bi = 0x7FFFFFFF;
#pragma unroll
    for (int i = 0; i < 8; i++) {
        if ((bits[i] >> 9) >= mant_t) {
            float s = ev[i] * rZ + gumbel_from_bits(bits[i]);
            if (s > best) { best = s; bi = tid * 8 + i; }
        }
    }
#pragma unroll
    for (int st = 16; st > 0; st >>= 1) {
        float ob = __shfl_xor_sync(0xffffffffu, best, st);
        int oj = __shfl_xor_sync(0xffffffffu, bi, st);
        if (ob > best || (ob == best && oj < bi)) { best = ob; bi = oj; }
    }
    if (lane == 0) { sBestW[wid] = best; sIdxW[wid] = bi; }
    __syncthreads();
    if (tid == 0) {
        float b = sBestW[0];
        int j = sIdxW[0];
#pragma unroll
        for (int w = 1; w < 8; w++) {
            float ob = sBestW[w]; int oj = sIdxW[w];
            if (ob > b || (ob == b && oj < j)) { b = ob; j = oj; }
        }
        g_idx[n] = j;
    }
}

// ---------------- K5/K6 ----------------
__global__ void __launch_bounds__(256) zero_acc_kernel() {
    g_acc[blockIdx.x * 256 + threadIdx.x] = 0.f;
}
__global__ void __launch_bounds__(256) scatter_kernel(const float* __restrict__ x1) {
    const int w = threadIdx.x >> 5;
    const int lane = threadIdx.x & 31;
    const int n = blockIdx.x * 8 + w;
    const int m = g_idx[n];
#pragma unroll
    for (int i = 0; i < 4; i++) {
        int d = lane + i * 32;
        atomicAdd(&g_acc[m * DIM + d], x1[(size_t)n * DIM + d]);
    }
}
__global__ void __launch_bounds__(128) final_kernel(const float* __restrict__ Wd,
                                                    const float* __restrict__ bd,
                                                    float* __restrict__ out) {
    const int m = blockIdx.x;
    const int j = threadIdx.x;
    __shared__ float a[DIM];
    a[j] = g_acc[m * DIM + j];
    __syncthreads();
    float s = bd[j];
#pragma unroll 8
    for (int kq = 0; kq < DIM; kq++) s = fmaf(a[kq], Wd[j * DIM + kq], s);
    out[m * DIM + j] = s;
}

// ---------------- launch ----------------
extern "C" void kernel_launch(void* const* d_in, const int* in_sizes, int n_in,
                              void* d_out, int out_size) {
    const float* x1 = (const float*)d_in[0];
    const float* k  = (const float*)d_in[1];
    const float* c  = (const float*)d_in[2];
    const float* Wq = (const float*)d_in[3];
    const float* bq = (const float*)d_in[4];
    const float* Wd = (const float*)d_in[5];
    const float* bd = (const float*)d_in[6];
    float* out = (float*)d_out;

    cudaFuncSetAttribute(logits_mma_kernel,
                         cudaFuncAttributeMaxDynamicSharedMemorySize, GEMM_SMEM_BYTES);

    prep_Wb_kernel<<<128, 128>>>(Wq, bq);
    prep_G_kernel<<<M_COLS, 128>>>(c);
    prep_A_kernel<<<(N_ROWS * DIM / 4) / 256, 256>>>(x1, k);
    prep_GG_kernel<<<(M_COLS * DIM / 4) / 256, 256>>>();
    dim3 gl(M_COLS / 64, N_ROWS / 128);
    logits_mma_kernel<<<gl, 256, GEMM_SMEM_BYTES>>>();
    softmax_argmax_kernel<<<N_ROWS, 256>>>();
    zero_acc_kernel<<<M_COLS * DIM / 256, 256>>>();
    scatter_kernel<<<N_ROWS / 8, 256>>>(x1);
    final_kernel<<<M_COLS, 128>>>(Wd, bd, out);
}